// round 5
// baseline (speedup 1.0000x reference)
#include <cuda_runtime.h>
#include <math.h>

#define Bdim 64
#define Sdim 1024
#define Idim 1024
#define Hdim 1024
#define NB_REC 128
#define REC_THREADS 512

// Scratch (allocation-free rule: __device__ globals)
__device__ float g_hbuf3[3][Bdim * Hdim];   // triple-buffered h (mod-3 step)
__device__ unsigned g_flags[NB_REC * 32];   // per-CTA publish flag, 128B stride

typedef unsigned long long ull;

// ---------------------------------------------------------------------------
// packed f32x2 FMA (Blackwell): 2x fp32 FMA throughput
// ---------------------------------------------------------------------------
__device__ __forceinline__ void fma2(ull& c, ull a, ull b) {
    asm("fma.rn.f32x2 %0, %1, %2, %0;" : "+l"(c) : "l"(a), "l"(b));
}
__device__ __forceinline__ float f2sum(ull v) {
    float2 f = *reinterpret_cast<float2*>(&v);
    return f.x + f.y;
}
__device__ __forceinline__ void cp16(void* d, const void* s) {
    unsigned sd = (unsigned)__cvta_generic_to_shared(d);
    asm volatile("cp.async.cg.shared.global [%0], [%1], 16;" :: "r"(sd), "l"(s));
}
#define CP_COMMIT() asm volatile("cp.async.commit_group;")
#define CP_WAIT(n) asm volatile("cp.async.wait_group %0;" :: "n"(n))

__device__ __forceinline__ void flag_release(unsigned* p, unsigned v) {
    asm volatile("st.release.gpu.u32 [%0], %1;" :: "l"(p), "r"(v) : "memory");
}
__device__ __forceinline__ void flag_wait(const unsigned* p, unsigned need) {
    unsigned v;
    do {
        asm volatile("ld.acquire.gpu.u32 %0, [%1];" : "=r"(v) : "l"(p) : "memory");
    } while (v < need);
}

// ---------------------------------------------------------------------------
__global__ void reset_state() {
    int i = blockIdx.x * blockDim.x + threadIdx.x;
    for (; i < NB_REC * 32; i += gridDim.x * blockDim.x) g_flags[i] = 0;
}

__global__ void copy_h(const float* __restrict__ hin) {
    int i = blockIdx.x * blockDim.x + threadIdx.x;
    for (; i < Bdim * Hdim; i += gridDim.x * blockDim.x) g_hbuf3[0][i] = hin[i];
}

// ---------------------------------------------------------------------------
// Phase 1: wx = X @ Wih^T + b   (M=65536, N=1024, K=1024)
// CTA tile 128m x 64n, 256 threads, thread tile 8m x 4n (f32x2 along k),
// k-chunk 16, cp.async double-buffered. (unchanged from R4 — passed)
// ---------------------------------------------------------------------------
__global__ __launch_bounds__(256) void wx_gemm(const float* __restrict__ X,
                                               const float* __restrict__ W,
                                               const float* __restrict__ bias,
                                               float* __restrict__ out) {
    __shared__ float As[2][128 * 20];
    __shared__ float Ws[2][64 * 20];
    const int tid = threadIdx.x;
    const int tm = tid >> 4, tn = tid & 15;
    const long mBase = (long)blockIdx.y * 128;
    const int nBase = blockIdx.x * 64;

    const int xr = tid >> 1, xq = (tid & 1) * 8;
    const float* xg = X + (mBase + xr) * Idim + xq;
    const int wr = tid >> 2, wq = (tid & 3) * 4;
    const float* wg = W + (nBase + wr) * Idim + wq;

    ull acc[8][4];
#pragma unroll
    for (int i = 0; i < 8; i++)
#pragma unroll
        for (int j = 0; j < 4; j++) acc[i][j] = 0ull;

    cp16(&As[0][xr * 20 + xq], xg);
    cp16(&As[0][xr * 20 + xq + 4], xg + 4);
    cp16(&Ws[0][wr * 20 + wq], wg);
    CP_COMMIT();

    int buf = 0;
    for (int kt = 0; kt < Idim / 16; kt++) {
        if (kt + 1 < Idim / 16) {
            const int k0 = (kt + 1) * 16;
            cp16(&As[buf ^ 1][xr * 20 + xq], xg + k0);
            cp16(&As[buf ^ 1][xr * 20 + xq + 4], xg + k0 + 4);
            cp16(&Ws[buf ^ 1][wr * 20 + wq], wg + k0);
        }
        CP_COMMIT();
        CP_WAIT(1);
        __syncthreads();

        const float* A = &As[buf][tm * 8 * 20];
        const float* Bp = &Ws[buf][tn * 20];
#pragma unroll
        for (int q = 0; q < 4; q++) {
            ulonglong2 bt[4];
#pragma unroll
            for (int j = 0; j < 4; j++)
                bt[j] = *reinterpret_cast<const ulonglong2*>(&Bp[j * 320 + q * 4]);
#pragma unroll
            for (int i = 0; i < 8; i++) {
                ulonglong2 at =
                    *reinterpret_cast<const ulonglong2*>(&A[i * 20 + q * 4]);
#pragma unroll
                for (int j = 0; j < 4; j++) fma2(acc[i][j], at.x, bt[j].x);
#pragma unroll
                for (int j = 0; j < 4; j++) fma2(acc[i][j], at.y, bt[j].y);
            }
        }
        __syncthreads();
        buf ^= 1;
    }

#pragma unroll
    for (int j = 0; j < 4; j++) {
        float bv = bias[nBase + tn + 16 * j];
#pragma unroll
        for (int i = 0; i < 8; i++) {
            out[(mBase + tm * 8 + i) * Hdim + nBase + tn + 16 * j] =
                f2sum(acc[i][j]) + bv;
        }
    }
}

// ---------------------------------------------------------------------------
// Phase 2: persistent recurrence with DATAFLOW sync (no global barrier).
// 128 CTAs x 512 threads. CTA = 32 cols x 16 batches; 4 batch groups x 32 CTAs.
// Warp w consumes h[batchBase..+16, 64w..64w+64) = tiles of producer CTAs
// (grp + 2w) and (grp + 2w + 1) only: poll 2 flags, stage own 4KB, compute.
// Producers publish their 2KB h tile + release-flag each step.
// Triple-buffered h (max producer/consumer lag = 2 steps < 3 buffers).
// ---------------------------------------------------------------------------
__global__ __launch_bounds__(REC_THREADS, 1)
void rnn_recur(const float* __restrict__ Whh, const float* __restrict__ bhh,
               float* __restrict__ y, float* __restrict__ hlast) {
    extern __shared__ float sm[];
    float* sW = sm;                  // 32 x 1028
    float* sH = sm + 32 * 1028;      // 16 x 1028
    float* sRed = sH;                // overlay: 16 x 640 (after all sH reads)

    const int tid = threadIdx.x;
    const int bid = blockIdx.x;
    const int colBase = (bid & 31) * 32;
    const int batchBase = (bid >> 5) * 16;
    const int grpBase = bid & ~31;

    // cache Whh slice once: 32 rows x 1024 cols = 8192 four-float chunks
#pragma unroll
    for (int i = 0; i < 16; i++) {
        int chunk = tid + i * REC_THREADS;
        int r = chunk >> 8, off = (chunk & 255) * 4;
        *reinterpret_cast<float4*>(&sW[r * 1028 + off]) =
            *reinterpret_cast<const float4*>(&Whh[(colBase + r) * Hdim + off]);
    }

    const int wid = tid >> 5, lane = tid & 31;
    const int cpos = lane & 7;   // col group: cols cpos + 8*ci
    const int bpos = lane >> 3;  // batch group: batches bpos + 4*bi
    const int kBase = wid * 64;

    // this warp's two producers' flags
    const unsigned* flag0 = &g_flags[(grpBase + 2 * wid) * 32];
    const unsigned* flag1 = &g_flags[(grpBase + 2 * wid + 1) * 32];
    unsigned* myflag = &g_flags[bid * 32];

    // per-warp staging map: 256 chunks of 16B (16 rows x 64 floats)
    const int srow = lane >> 2;          // chunks per row = 16; 8 chunks/lane:
    const int soff0 = (lane & 3) * 16;   // chunk = lane + i*32 -> row=chunk>>4

    // finish-stage: one output per thread
    const int ob = tid >> 5;  // batch 0..15
    const int oc = tid & 31;  // col 0..31
    const float bv = bhh[colBase + oc];
    const long ybase = (((long)(batchBase + ob)) << 20) + colBase + oc;
    const int hoff = ((batchBase + ob) << 10) + colBase + oc;
    const int rbase = ob * 40 + oc;  // sRed read base
    float hv = 0.f;

    int cur = 0;  // s % 3
    for (int s = 0; s < Sdim; s++) {
        const int nxt = (cur == 2) ? 0 : cur + 1;
        float wxv = __ldg(&y[ybase + ((long)s << 10)]);  // prefetch wx (indep)

        // wait for this warp's two producers to publish step s
        if (lane == 0) {
            flag_wait(flag0, (unsigned)s);
            flag_wait(flag1, (unsigned)s);
        }
        __syncwarp();

        // stage own 4KB slice: h[batchBase..+16, kBase..kBase+64)
        const float* hsrc = g_hbuf3[cur];
#pragma unroll
        for (int i = 0; i < 8; i++) {
            int chunk = lane + i * 32;
            int r = chunk >> 4, koff = (chunk & 15) * 4;
            cp16(&sH[r * 1028 + kBase + koff],
                 &hsrc[((batchBase + r) << 10) + kBase + koff]);
        }
        CP_COMMIT();
        CP_WAIT(0);
        __syncwarp();

        ull acc[4][4];
#pragma unroll
        for (int ci = 0; ci < 4; ci++)
#pragma unroll
            for (int bi = 0; bi < 4; bi++) acc[ci][bi] = 0ull;

#pragma unroll 4
        for (int q = 0; q < 16; q++) {
            const int k = kBase + q * 4;
            ulonglong2 wf[4], hf[4];
#pragma unroll
            for (int ci = 0; ci < 4; ci++)
                wf[ci] = *reinterpret_cast<const ulonglong2*>(
                    &sW[(cpos + 8 * ci) * 1028 + k]);
#pragma unroll
            for (int bi = 0; bi < 4; bi++)
                hf[bi] = *reinterpret_cast<const ulonglong2*>(
                    &sH[(bpos + 4 * bi) * 1028 + k]);
#pragma unroll
            for (int ci = 0; ci < 4; ci++)
#pragma unroll
                for (int bi = 0; bi < 4; bi++) fma2(acc[ci][bi], hf[bi].x, wf[ci].x);
#pragma unroll
            for (int ci = 0; ci < 4; ci++)
#pragma unroll
                for (int bi = 0; bi < 4; bi++) fma2(acc[ci][bi], hf[bi].y, wf[ci].y);
        }
        __syncthreads();  // all warps' sH reads done before sRed overlay writes

#pragma unroll
        for (int ci = 0; ci < 4; ci++)
#pragma unroll
            for (int bi = 0; bi < 4; bi++) {
                sRed[wid * 640 + (bpos + 4 * bi) * 40 + cpos + 8 * ci] =
                    f2sum(acc[ci][bi]);
            }
        __syncthreads();

        float sum = 0.f;
#pragma unroll
        for (int w = 0; w < 16; w++) sum += sRed[w * 640 + rbase];

        hv = tanhf(wxv + sum + bv);
        g_hbuf3[nxt][hoff] = hv;          // publish h tile (plain STG -> L2)
        y[ybase + ((long)s << 10)] = hv;  // y output
        __syncthreads();                  // CTA-wide: tile fully stored
        if (tid == 0) flag_release(myflag, (unsigned)(s + 1));
        cur = nxt;
    }

    hlast[hoff] = hv;  // final h of this thread's (b,c) slot
}

// ---------------------------------------------------------------------------
extern "C" void kernel_launch(void* const* d_in, const int* in_sizes, int n_in,
                              void* d_out, int out_size) {
    const float* x = (const float*)d_in[0];      // [B,S,I]
    const float* h0 = (const float*)d_in[1];     // [B,H]
    const float* Wih_w = (const float*)d_in[2];  // [H,I]
    const float* Wih_b = (const float*)d_in[3];  // [H]
    const float* Whh_w = (const float*)d_in[4];  // [H,H]
    const float* Whh_b = (const float*)d_in[5];  // [H]
    float* y = (float*)d_out;                       // [B,S,H]
    float* hlast = y + (size_t)Bdim * Sdim * Hdim;  // [B,H]

    const int smem_bytes = (32 + 16) * 1028 * 4;  // 197376
    cudaFuncSetAttribute(rnn_recur, cudaFuncAttributeMaxDynamicSharedMemorySize,
                         smem_bytes);

    reset_state<<<8, 256>>>();
    copy_h<<<64, 256>>>(h0);
    wx_gemm<<<dim3(Hdim / 64, (Bdim * Sdim) / 128), 256>>>(x, Wih_w, Wih_b, y);
    rnn_recur<<<NB_REC, REC_THREADS, smem_bytes>>>(Whh_w, Whh_b, y, hlast);
}

// round 6
// speedup vs baseline: 1.1880x; 1.1880x over previous
#include <cuda_runtime.h>
#include <math.h>

#define Bdim 64
#define Sdim 1024
#define Idim 1024
#define Hdim 1024
#define NB_REC 128
#define REC_THREADS 512

// Scratch (allocation-free rule: __device__ globals)
__device__ float g_hbuf[2][Bdim * Hdim];
__device__ unsigned g_cnt;
__device__ unsigned g_flag;

typedef unsigned long long ull;

// ---------------------------------------------------------------------------
__device__ __forceinline__ void fma2(ull& c, ull a, ull b) {
    asm("fma.rn.f32x2 %0, %1, %2, %0;" : "+l"(c) : "l"(a), "l"(b));
}
__device__ __forceinline__ float f2sum(ull v) {
    float2 f = *reinterpret_cast<float2*>(&v);
    return f.x + f.y;
}
__device__ __forceinline__ void cp16(void* d, const void* s) {
    unsigned sd = (unsigned)__cvta_generic_to_shared(d);
    asm volatile("cp.async.cg.shared.global [%0], [%1], 16;" :: "r"(sd), "l"(s));
}
#define CP_COMMIT() asm volatile("cp.async.commit_group;")
#define CP_WAIT(n) asm volatile("cp.async.wait_group %0;" :: "n"(n))

// bulk async copy global->shared, completion via mbarrier tx-count
__device__ __forceinline__ void bulk_g2s(unsigned dst, const void* src,
                                         unsigned bytes, unsigned mbar) {
    asm volatile(
        "cp.async.bulk.shared::cluster.global.mbarrier::complete_tx::bytes "
        "[%0], [%1], %2, [%3];"
        :: "r"(dst), "l"(src), "r"(bytes), "r"(mbar) : "memory");
}
__device__ __forceinline__ void mbar_init(unsigned mbar, unsigned cnt) {
    asm volatile("mbarrier.init.shared.b64 [%0], %1;" :: "r"(mbar), "r"(cnt)
                 : "memory");
}
__device__ __forceinline__ void mbar_expect_tx(unsigned mbar, unsigned tx) {
    asm volatile("mbarrier.arrive.expect_tx.shared.b64 _, [%0], %1;"
                 :: "r"(mbar), "r"(tx) : "memory");
}
__device__ __forceinline__ void mbar_wait(unsigned mbar, unsigned parity) {
    asm volatile(
        "{\n\t"
        ".reg .pred P1;\n\t"
        "WAIT_LOOP_%=:\n\t"
        "mbarrier.try_wait.parity.acquire.cta.shared::cta.b64 P1, [%0], %1, 0x989680;\n\t"
        "@P1 bra.uni WAIT_DONE_%=;\n\t"
        "bra.uni WAIT_LOOP_%=;\n\t"
        "WAIT_DONE_%=:\n\t"
        "}"
        :: "r"(mbar), "r"(parity) : "memory");
}
__device__ __forceinline__ unsigned atom_add_release(unsigned* p, unsigned v) {
    unsigned old;
    asm volatile("atom.add.release.gpu.u32 %0, [%1], %2;"
                 : "=r"(old) : "l"(p), "r"(v) : "memory");
    return old;
}
__device__ __forceinline__ void st_release(unsigned* p, unsigned v) {
    asm volatile("st.release.gpu.u32 [%0], %1;" :: "l"(p), "r"(v) : "memory");
}
__device__ __forceinline__ unsigned ld_acquire(const unsigned* p) {
    unsigned v;
    asm volatile("ld.acquire.gpu.u32 %0, [%1];" : "=r"(v) : "l"(p) : "memory");
    return v;
}

// ---------------------------------------------------------------------------
__global__ void reset_state() {
    if (threadIdx.x == 0) {
        g_cnt = 0;
        g_flag = 0;
    }
}

__global__ void copy_h(const float* __restrict__ hin) {
    int i = blockIdx.x * blockDim.x + threadIdx.x;
    for (; i < Bdim * Hdim; i += gridDim.x * blockDim.x) g_hbuf[0][i] = hin[i];
}

// ---------------------------------------------------------------------------
// Phase 1: wx = X @ Wih^T + b  (unchanged from R4 — measured good)
// ---------------------------------------------------------------------------
__global__ __launch_bounds__(256) void wx_gemm(const float* __restrict__ X,
                                               const float* __restrict__ W,
                                               const float* __restrict__ bias,
                                               float* __restrict__ out) {
    __shared__ float As[2][128 * 20];
    __shared__ float Ws[2][64 * 20];
    const int tid = threadIdx.x;
    const int tm = tid >> 4, tn = tid & 15;
    const long mBase = (long)blockIdx.y * 128;
    const int nBase = blockIdx.x * 64;

    const int xr = tid >> 1, xq = (tid & 1) * 8;
    const float* xg = X + (mBase + xr) * Idim + xq;
    const int wr = tid >> 2, wq = (tid & 3) * 4;
    const float* wg = W + (nBase + wr) * Idim + wq;

    ull acc[8][4];
#pragma unroll
    for (int i = 0; i < 8; i++)
#pragma unroll
        for (int j = 0; j < 4; j++) acc[i][j] = 0ull;

    cp16(&As[0][xr * 20 + xq], xg);
    cp16(&As[0][xr * 20 + xq + 4], xg + 4);
    cp16(&Ws[0][wr * 20 + wq], wg);
    CP_COMMIT();

    int buf = 0;
    for (int kt = 0; kt < Idim / 16; kt++) {
        if (kt + 1 < Idim / 16) {
            const int k0 = (kt + 1) * 16;
            cp16(&As[buf ^ 1][xr * 20 + xq], xg + k0);
            cp16(&As[buf ^ 1][xr * 20 + xq + 4], xg + k0 + 4);
            cp16(&Ws[buf ^ 1][wr * 20 + wq], wg + k0);
        }
        CP_COMMIT();
        CP_WAIT(1);
        __syncthreads();

        const float* A = &As[buf][tm * 8 * 20];
        const float* Bp = &Ws[buf][tn * 20];
#pragma unroll
        for (int q = 0; q < 4; q++) {
            ulonglong2 bt[4];
#pragma unroll
            for (int j = 0; j < 4; j++)
                bt[j] = *reinterpret_cast<const ulonglong2*>(&Bp[j * 320 + q * 4]);
#pragma unroll
            for (int i = 0; i < 8; i++) {
                ulonglong2 at =
                    *reinterpret_cast<const ulonglong2*>(&A[i * 20 + q * 4]);
#pragma unroll
                for (int j = 0; j < 4; j++) fma2(acc[i][j], at.x, bt[j].x);
#pragma unroll
                for (int j = 0; j < 4; j++) fma2(acc[i][j], at.y, bt[j].y);
            }
        }
        __syncthreads();
        buf ^= 1;
    }

#pragma unroll
    for (int j = 0; j < 4; j++) {
        float bv = bias[nBase + tn + 16 * j];
#pragma unroll
        for (int i = 0; i < 8; i++) {
            out[(mBase + tm * 8 + i) * Hdim + nBase + tn + 16 * j] =
                f2sum(acc[i][j]) + bv;
        }
    }
}

// ---------------------------------------------------------------------------
// Phase 2: persistent recurrence, R4 barrier + bulk-copy staging.
// 128 CTAs x 512 threads. CTA = 32 cols x 16 batches, Whh slice in smem.
// Per step: tid0 issues 16x cp.async.bulk (4KB rows, 64KB total, mbarrier tx)
//           -> all wait mbar -> FMA2 compute (floor 4096cyc) -> sRed reduce
//           -> tanh -> publish h -> single release-atomic grid barrier.
// ---------------------------------------------------------------------------
__global__ __launch_bounds__(REC_THREADS, 1)
void rnn_recur(const float* __restrict__ Whh, const float* __restrict__ bhh,
               float* __restrict__ y, float* __restrict__ hlast) {
    extern __shared__ float sm[];
    float* sW = sm;                  // 32 x 1028
    float* sH = sm + 32 * 1028;      // 16 x 1028
    float* sRed = sH;                // overlay: 16 x 640 (after all sH reads)
    __shared__ unsigned long long mbar_storage;

    const int tid = threadIdx.x;
    const int bid = blockIdx.x;
    const int colBase = (bid & 31) * 32;
    const int batchBase = (bid >> 5) * 16;
    const unsigned mbar = (unsigned)__cvta_generic_to_shared(&mbar_storage);
    const unsigned sH_smem = (unsigned)__cvta_generic_to_shared(sH);

    if (tid == 0) mbar_init(mbar, 1);

    // cache Whh slice once: 32 rows x 1024 cols
#pragma unroll
    for (int i = 0; i < 16; i++) {
        int chunk = tid + i * REC_THREADS;
        int r = chunk >> 8, off = (chunk & 255) * 4;
        *reinterpret_cast<float4*>(&sW[r * 1028 + off]) =
            *reinterpret_cast<const float4*>(&Whh[(colBase + r) * Hdim + off]);
    }
    __syncthreads();  // mbar init + sW visible

    const int wid = tid >> 5, lane = tid & 31;
    const int cpos = lane & 7;   // col group: cols cpos + 8*ci
    const int bpos = lane >> 3;  // batch group: batches bpos + 4*bi
    const int kBase = wid * 64;

    const int ob = tid >> 5;  // batch 0..15
    const int oc = tid & 31;  // col 0..31
    const float bv = bhh[colBase + oc];
    const long ybase = (((long)(batchBase + ob)) << 20) + colBase + oc;
    const int hoff = ((batchBase + ob) << 10) + colBase + oc;
    const int rbase = ob * 40 + oc;
    float hv = 0.f;

    for (int s = 0; s < Sdim; s++) {
        const int p = s & 1;
        // stage h slice: 16 bulk copies of one 4KB row each
        if (tid == 0) {
            asm volatile("fence.proxy.async.shared::cta;" ::: "memory");
            mbar_expect_tx(mbar, 16 * 4096);
            const float* hsrc = g_hbuf[p] + ((long)batchBase << 10);
#pragma unroll
            for (int r = 0; r < 16; r++) {
                bulk_g2s(sH_smem + (unsigned)(r * 1028 * 4), hsrc + (r << 10),
                         4096, mbar);
            }
        }
        float wxv = __ldg(&y[ybase + ((long)s << 10)]);  // overlap with copy
        mbar_wait(mbar, (unsigned)p);

        ull acc[4][4];
#pragma unroll
        for (int ci = 0; ci < 4; ci++)
#pragma unroll
            for (int bi = 0; bi < 4; bi++) acc[ci][bi] = 0ull;

#pragma unroll 4
        for (int q = 0; q < 16; q++) {
            const int k = kBase + q * 4;
            ulonglong2 wf[4], hf[4];
#pragma unroll
            for (int ci = 0; ci < 4; ci++)
                wf[ci] = *reinterpret_cast<const ulonglong2*>(
                    &sW[(cpos + 8 * ci) * 1028 + k]);
#pragma unroll
            for (int bi = 0; bi < 4; bi++)
                hf[bi] = *reinterpret_cast<const ulonglong2*>(
                    &sH[(bpos + 4 * bi) * 1028 + k]);
#pragma unroll
            for (int ci = 0; ci < 4; ci++)
#pragma unroll
                for (int bi = 0; bi < 4; bi++) fma2(acc[ci][bi], hf[bi].x, wf[ci].x);
#pragma unroll
            for (int ci = 0; ci < 4; ci++)
#pragma unroll
                for (int bi = 0; bi < 4; bi++) fma2(acc[ci][bi], hf[bi].y, wf[ci].y);
        }
        __syncthreads();  // all sH reads done before sRed overlay writes

#pragma unroll
        for (int ci = 0; ci < 4; ci++)
#pragma unroll
            for (int bi = 0; bi < 4; bi++) {
                sRed[wid * 640 + (bpos + 4 * bi) * 40 + cpos + 8 * ci] =
                    f2sum(acc[ci][bi]);
            }
        __syncthreads();

        float sum = 0.f;
#pragma unroll
        for (int w = 0; w < 16; w++) sum += sRed[w * 640 + rbase];

        hv = tanhf(wxv + sum + bv);
        g_hbuf[1 - p][hoff] = hv;         // publish h
        y[ybase + ((long)s << 10)] = hv;  // y output
        __syncthreads();                  // CTA writes done before release
        if (tid == 0) {
            unsigned arrived = atom_add_release(&g_cnt, 1u) + 1u;
            unsigned step = (unsigned)(s + 1);
            if (arrived == step * (unsigned)NB_REC) st_release(&g_flag, step);
            while (ld_acquire(&g_flag) < step) {
            }
        }
        __syncthreads();
    }

    hlast[hoff] = hv;
}

// ---------------------------------------------------------------------------
extern "C" void kernel_launch(void* const* d_in, const int* in_sizes, int n_in,
                              void* d_out, int out_size) {
    const float* x = (const float*)d_in[0];      // [B,S,I]
    const float* h0 = (const float*)d_in[1];     // [B,H]
    const float* Wih_w = (const float*)d_in[2];  // [H,I]
    const float* Wih_b = (const float*)d_in[3];  // [H]
    const float* Whh_w = (const float*)d_in[4];  // [H,H]
    const float* Whh_b = (const float*)d_in[5];  // [H]
    float* y = (float*)d_out;                       // [B,S,H]
    float* hlast = y + (size_t)Bdim * Sdim * Hdim;  // [B,H]

    const int smem_bytes = (32 + 16) * 1028 * 4;  // 197376
    cudaFuncSetAttribute(rnn_recur, cudaFuncAttributeMaxDynamicSharedMemorySize,
                         smem_bytes);

    reset_state<<<1, 32>>>();
    copy_h<<<64, 256>>>(h0);
    wx_gemm<<<dim3(Hdim / 64, (Bdim * Sdim) / 128), 256>>>(x, Wih_w, Wih_b, y);
    rnn_recur<<<NB_REC, REC_THREADS, smem_bytes>>>(Whh_w, Whh_b, y, hlast);
}